// round 3
// baseline (speedup 1.0000x reference)
#include <cuda_runtime.h>
#include <cstdint>

// Problem constants (fixed shapes from reference)
#define NUM_VERTS 6890
#define NUM_FACES 13776
#define IMG_H 1024
#define IMG_W 1024
#define NBATCH 16
#define HW (IMG_H * IMG_W)
#define PLANE_FLOATS (HW * 3)  // floats per batch plane = 3,145,728

// Indices are INT32: JAX with x64 disabled downcasts jnp.int64 -> int32,
// so face_tensor and pix_to_face arrive as int32 buffers.
//
// Each thread handles 4 consecutive pixels:
//   - bary:  12 consecutive floats -> 3x float4 loads
//   - pix:   4 consecutive int32   -> 1x int4 load
//   - out:   12 floats per batch   -> 3x float4 stores, x16 batches
// The pixel gather only ever touches batch-0 vertex attributes (reference
// replicates its indexing bug faithfully: no per-batch face offset in the
// pixel path, and batch-0 vertex offset is 0), and the output is one
// (H,W,3) plane broadcast to all 16 batches. Compute once, fan out stores.
__global__ void __launch_bounds__(256) uv_render_kernel(
    const float* __restrict__ verts,   // (N, V, 3) f32 — only batch 0 used
    const int*   __restrict__ faces,   // (F, 3) i32
    const int*   __restrict__ pix,     // (H*W) i32
    const float* __restrict__ bary,    // (H*W, 3) f32
    float* __restrict__ out)           // (16, H, W, 3) f32
{
    const int t = blockIdx.x * blockDim.x + threadIdx.x;
    const int p0 = t * 4;
    if (p0 >= HW) return;

    // ---- Loads (all 16B-aligned) ----
    const float4* b4 = reinterpret_cast<const float4*>(bary + (size_t)p0 * 3);
    const float4 bA = b4[0];
    const float4 bB = b4[1];
    const float4 bC = b4[2];

    const int4 px = *reinterpret_cast<const int4*>(pix + p0);

    const int pf[4] = { px.x, px.y, px.z, px.w };
    const float bw[4][3] = {
        { bA.x, bA.y, bA.z },
        { bA.w, bB.x, bB.y },
        { bB.z, bB.w, bC.x },
        { bC.y, bC.z, bC.w }
    };

    // ---- Compute 4 pixels -> 12 floats ----
    float vals[12];
    #pragma unroll
    for (int i = 0; i < 4; i++) {
        float r0 = 0.0f, r1 = 0.0f, r2 = 0.0f;
        const int f = pf[i];
        if (f >= 0) {
            const int fb = f * 3;
            #pragma unroll
            for (int k = 0; k < 3; k++) {
                const int vi = faces[fb + k];        // vertex index (batch-0)
                const float* va = verts + (size_t)vi * 3;
                const float w = bw[i][k];
                r0 = fmaf(w, va[0], r0);
                r1 = fmaf(w, va[1], r1);
                r2 = fmaf(w, va[2], r2);
            }
        }
        vals[i * 3 + 0] = r0;
        vals[i * 3 + 1] = r1;
        vals[i * 3 + 2] = r2;
    }

    const float4 o0 = make_float4(vals[0], vals[1], vals[2],  vals[3]);
    const float4 o1 = make_float4(vals[4], vals[5], vals[6],  vals[7]);
    const float4 o2 = make_float4(vals[8], vals[9], vals[10], vals[11]);

    // ---- Broadcast store to all 16 batch planes ----
    const size_t base = (size_t)p0 * 3;
    #pragma unroll
    for (int b = 0; b < NBATCH; b++) {
        float4* o = reinterpret_cast<float4*>(out + (size_t)b * PLANE_FLOATS + base);
        o[0] = o0;
        o[1] = o1;
        o[2] = o2;
    }
}

extern "C" void kernel_launch(void* const* d_in, const int* in_sizes, int n_in,
                              void* d_out, int out_size)
{
    // metadata order: verts_attr (f32), face_tensor (i32), pix_to_face (i32), bary_coords (f32)
    const float* verts = (const float*)d_in[0];
    const int*   faces = (const int*)d_in[1];
    const int*   pix   = (const int*)d_in[2];
    const float* bary  = (const float*)d_in[3];
    float* out = (float*)d_out;

    const int threads = 256;
    const int total_threads = HW / 4;            // 262144
    const int blocks = total_threads / threads;  // 1024
    uv_render_kernel<<<blocks, threads>>>(verts, faces, pix, bary, out);
}

// round 4
// speedup vs baseline: 1.7416x; 1.7416x over previous
#include <cuda_runtime.h>
#include <cstdint>

// Problem constants
#define NUM_VERTS 6890
#define NUM_FACES 13776
#define IMG_H 1024
#define IMG_W 1024
#define NBATCH 16
#define HW (IMG_H * IMG_W)
#define PLANE_FLOATS (HW * 3)     // 3,145,728 floats per batch plane
#define PIX_PER_BLOCK 1024        // 256 threads x 4 pixels
#define SEG_FLOATS (PIX_PER_BLOCK * 3)   // 3072 floats = 12KB smem

// Precomputed per-face vertex attributes, 64B-aligned rows:
// row f = { v0.xyz _, v1.xyz _, v2.xyz _, pad } (4 x float4)
// 13776 * 64B = 882 KB -> L2-resident across the render kernel.
__device__ float4 g_face_attr[NUM_FACES][4];

// Kernel A: build the face-attr table (batch-0 vertices only; the reference's
// pixel gather never applies a per-batch face offset, and batch-0 vertex
// offset is 0, so only batch 0 matters).
__global__ void __launch_bounds__(128) build_face_attr(
    const float* __restrict__ verts,   // (N, V, 3) f32
    const int*   __restrict__ faces)   // (F, 3) i32
{
    const int f = blockIdx.x * blockDim.x + threadIdx.x;
    if (f >= NUM_FACES) return;
    const int i0 = faces[f * 3 + 0];
    const int i1 = faces[f * 3 + 1];
    const int i2 = faces[f * 3 + 2];
    const float* v0 = verts + (size_t)i0 * 3;
    const float* v1 = verts + (size_t)i1 * 3;
    const float* v2 = verts + (size_t)i2 * 3;
    g_face_attr[f][0] = make_float4(v0[0], v0[1], v0[2], 0.0f);
    g_face_attr[f][1] = make_float4(v1[0], v1[1], v1[2], 0.0f);
    g_face_attr[f][2] = make_float4(v2[0], v2[1], v2[2], 0.0f);
    g_face_attr[f][3] = make_float4(0.0f, 0.0f, 0.0f, 0.0f);
}

// Kernel B: interpolate per pixel, stage the block's (1024-pixel, 12KB)
// output segment in smem, then broadcast-copy to all 16 batch planes with
// fully coalesced float4 streaming stores.
__global__ void __launch_bounds__(256) render_kernel(
    const int*   __restrict__ pix,     // (H*W) i32
    const float* __restrict__ bary,    // (H*W, 3) f32
    float* __restrict__ out)           // (16, H, W, 3) f32
{
    __shared__ float seg[SEG_FLOATS];

    const int tid = threadIdx.x;
    const int p0  = blockIdx.x * PIX_PER_BLOCK + tid * 4;   // 4 pixels/thread

    // ---- Coalesced input loads ----
    const float4* b4 = reinterpret_cast<const float4*>(bary + (size_t)p0 * 3);
    const float4 bA = b4[0];
    const float4 bB = b4[1];
    const float4 bC = b4[2];
    const int4 px = *reinterpret_cast<const int4*>(pix + p0);

    const int pf[4] = { px.x, px.y, px.z, px.w };
    const float bw[4][3] = {
        { bA.x, bA.y, bA.z },
        { bA.w, bB.x, bB.y },
        { bB.z, bB.w, bC.x },
        { bC.y, bC.z, bC.w }
    };

    // ---- Compute 4 pixels; write into smem segment ----
    float* sp = seg + tid * 12;
    #pragma unroll
    for (int i = 0; i < 4; i++) {
        float r0 = 0.0f, r1 = 0.0f, r2 = 0.0f;
        const int f = pf[i];
        if (f >= 0) {
            // 3 x LDG.128 from a 64B-aligned row; table is L2-resident.
            const float4 v0 = __ldg(&g_face_attr[f][0]);
            const float4 v1 = __ldg(&g_face_attr[f][1]);
            const float4 v2 = __ldg(&g_face_attr[f][2]);
            const float w0 = bw[i][0], w1 = bw[i][1], w2 = bw[i][2];
            r0 = fmaf(w2, v2.x, fmaf(w1, v1.x, w0 * v0.x));
            r1 = fmaf(w2, v2.y, fmaf(w1, v1.y, w0 * v0.y));
            r2 = fmaf(w2, v2.z, fmaf(w1, v1.z, w0 * v0.z));
        }
        sp[i * 3 + 0] = r0;
        sp[i * 3 + 1] = r1;
        sp[i * 3 + 2] = r2;
    }
    __syncthreads();

    // ---- Broadcast segment to all 16 batch planes, fully coalesced ----
    const float4* s4 = reinterpret_cast<const float4*>(seg);   // 768 float4
    const size_t seg_base4 = (size_t)blockIdx.x * (SEG_FLOATS / 4);
    float4* o4 = reinterpret_cast<float4*>(out);
    #pragma unroll
    for (int b = 0; b < NBATCH; b++) {
        float4* dst = o4 + (size_t)b * (PLANE_FLOATS / 4) + seg_base4;
        #pragma unroll
        for (int j = 0; j < SEG_FLOATS / 4 / 256; j++) {       // 3 iters
            __stcs(&dst[tid + j * 256], s4[tid + j * 256]);
        }
    }
}

extern "C" void kernel_launch(void* const* d_in, const int* in_sizes, int n_in,
                              void* d_out, int out_size)
{
    // metadata order: verts_attr (f32), face_tensor (i32), pix_to_face (i32), bary_coords (f32)
    const float* verts = (const float*)d_in[0];
    const int*   faces = (const int*)d_in[1];
    const int*   pix   = (const int*)d_in[2];
    const float* bary  = (const float*)d_in[3];
    float* out = (float*)d_out;

    build_face_attr<<<(NUM_FACES + 127) / 128, 128>>>(verts, faces);
    render_kernel<<<HW / PIX_PER_BLOCK, 256>>>(pix, bary, out);  // 1024 blocks
}